// round 1
// baseline (speedup 1.0000x reference)
#include <cuda_runtime.h>

// Problem constants
#define NN   4
#define SF   4
#define CC   3
#define HH   192
#define WW   192
#define RWO  190                 // Ho = Wo = H - 3 + 1
#define PP   (RWO * RWO)         // 36100 patches per (n, sf)
#define HW   (HH * WW)           // 36864

// Entropy constants (bandwidth h = 0.1, M = 9):
//   H = log(9) + 0.5*C*log(2*pi*h^2) - (1/9) * log( prod_i s_i )
//   log(9)                 =  2.1972245773
//   1.5*log(2*pi*0.01)     = -4.1509788938   (C = 3, marginal)
//   3.0*log(2*pi*0.01)     = -8.3019577875   (C = 6, joint)
#define CONST_MARG  (-1.9537543165f)   // log9 + 1.5*log(2*pi*h^2)
#define CONST_JOINT (-6.1047332102f)   // log9 + 3.0*log(2*pi*h^2)
#define INV2H2      50.0f              // 1/(2*h*h)
#define NINTH       (1.0f / 9.0f)

__global__ void zero_out_kernel(float* __restrict__ out, int n)
{
    int i = blockIdx.x * blockDim.x + threadIdx.x;
    if (i < n) out[i] = 0.0f;
}

// Entropy from row-sum vector s[9] (each s_i = sum_j exp(-d2_ij/(2h^2)), diag included)
__device__ __forceinline__ float entropy9(const float s[9], float cconst)
{
    float pr = ((s[0] * s[1]) * (s[2] * s[3])) *
               ((s[4] * s[5]) * (s[6] * s[7])) * s[8];
    return cconst - NINTH * __logf(pr);
}

__global__ void __launch_bounds__(128)
joint_entropy_kernel(const float* __restrict__ in, float* __restrict__ out)
{
    int t = blockIdx.x * blockDim.x + threadIdx.x;
    if (t >= NN * PP) return;

    int n  = t / PP;
    int p  = t - n * PP;
    int ho = p / RWO;
    int wo = p - ho * RWO;

    // Output interior location (pad = 1)
    int out_xy = (ho + 1) * WW + (wo + 1);

    float e_prev[36];   // exp(-50*d2) for previous frame's patch, 36 off-diag pairs
    float e_cur[36];

    #pragma unroll
    for (int sf = 0; sf < SF; ++sf) {
        // ---- load 9 points x 3 channels of this frame's patch ----
        const float* base = in + ((long)(n * SF + sf) * CC) * HW + ho * WW + wo;
        float pts[9][3];
        #pragma unroll
        for (int c = 0; c < CC; ++c) {
            const float* bc = base + c * HW;
            #pragma unroll
            for (int dy = 0; dy < 3; ++dy) {
                #pragma unroll
                for (int dx = 0; dx < 3; ++dx) {
                    pts[dy * 3 + dx][c] = bc[dy * WW + dx];
                }
            }
        }

        // ---- pairwise exponentials + marginal row sums ----
        float s[9];
        #pragma unroll
        for (int i = 0; i < 9; ++i) s[i] = 1.0f;   // diagonal term exp(0)

        int k = 0;
        #pragma unroll
        for (int i = 0; i < 9; ++i) {
            #pragma unroll
            for (int j = i + 1; j < 9; ++j) {
                float d0 = pts[i][0] - pts[j][0];
                float d1 = pts[i][1] - pts[j][1];
                float d2 = pts[i][2] - pts[j][2];
                float dd = d0 * d0 + d1 * d1 + d2 * d2;
                float ee = __expf(-INV2H2 * dd);
                e_cur[k] = ee;
                s[i] += ee;
                s[j] += ee;
                ++k;
            }
        }

        // marginal entropy for this frame
        float hm = entropy9(s, CONST_MARG);
        out[((long)(n * SF + sf) * 2 + 0) * HW + out_xy] = hm;

        // ---- joint entropy for the PREVIOUS frame: e_joint = e_prev * e_cur ----
        if (sf > 0) {
            float sj[9];
            #pragma unroll
            for (int i = 0; i < 9; ++i) sj[i] = 1.0f;
            int kk = 0;
            #pragma unroll
            for (int i = 0; i < 9; ++i) {
                #pragma unroll
                for (int j = i + 1; j < 9; ++j) {
                    float ej = e_prev[kk] * e_cur[kk];
                    sj[i] += ej;
                    sj[j] += ej;
                    ++kk;
                }
            }
            float hj = entropy9(sj, CONST_JOINT);
            out[((long)(n * SF + (sf - 1)) * 2 + 1) * HW + out_xy] = hj;
        }

        #pragma unroll
        for (int q = 0; q < 36; ++q) e_prev[q] = e_cur[q];
    }

    // ---- last frame pairs with itself: e_joint = e_prev^2 ----
    {
        float sj[9];
        #pragma unroll
        for (int i = 0; i < 9; ++i) sj[i] = 1.0f;
        int kk = 0;
        #pragma unroll
        for (int i = 0; i < 9; ++i) {
            #pragma unroll
            for (int j = i + 1; j < 9; ++j) {
                float ej = e_prev[kk] * e_prev[kk];
                sj[i] += ej;
                sj[j] += ej;
                ++kk;
            }
        }
        float hj = entropy9(sj, CONST_JOINT);
        out[((long)(n * SF + (SF - 1)) * 2 + 1) * HW + out_xy] = hj;
    }
}

extern "C" void kernel_launch(void* const* d_in, const int* in_sizes, int n_in,
                              void* d_out, int out_size)
{
    const float* in = (const float*)d_in[0];
    float* out = (float*)d_out;

    // Zero the whole output first (borders stay zero; poisoned otherwise)
    {
        int threads = 256;
        int blocks = (out_size + threads - 1) / threads;
        zero_out_kernel<<<blocks, threads>>>(out, out_size);
    }

    // Compute interior entropies
    {
        int total = NN * PP;          // 144400 threads
        int threads = 128;
        int blocks = (total + threads - 1) / threads;
        joint_entropy_kernel<<<blocks, threads>>>(in, out);
    }
}

// round 2
// speedup vs baseline: 1.1391x; 1.1391x over previous
#include <cuda_runtime.h>

// Problem: (4,4,3,192,192) fp32 -> (4,4,2,192,192) per-patch KDE entropies.
#define NN  4
#define SFN 4
#define CCH 3
#define HH  192
#define WW  192
#define HW  (HH * WW)

// H = log(9) + (C/2)*log(2*pi*h^2) - (1/9) * sum_i log(s_i), h = 0.1
//   log 9           =  2.19722457734
//   ln(2*pi*0.01)   = -2.76729311963
#define CM     (-1.9537151021f)   // log9 + 1.5*ln(2*pi*h^2)   (C=3 marginal)
#define CJ     (-6.1046547815f)   // log9 + 3.0*ln(2*pi*h^2)   (C=6 joint)
#define LN2_9  (0.0770163534f)    // ln(2)/9
#define PSC    (8.4932183f)       // sqrt(50 * log2(e)); pre-scale so exp(-50*d2) = ex2(-|d'|^2)

static __device__ __forceinline__ float fast_ex2(float x)
{
    float r;
    asm("ex2.approx.ftz.f32 %0, %1;" : "=f"(r) : "f"(x));
    return r;
}

static __device__ __forceinline__ float fast_lg2(float x)
{
    float r;
    asm("lg2.approx.f32 %0, %1;" : "=f"(r) : "f"(x));
    return r;
}

static __device__ __forceinline__ void load_pts(const float* __restrict__ b, float p[9][3])
{
    #pragma unroll
    for (int c = 0; c < 3; ++c) {
        const float* bc = b + c * HW;
        #pragma unroll
        for (int dy = 0; dy < 3; ++dy)
            #pragma unroll
            for (int dx = 0; dx < 3; ++dx)
                p[dy * 3 + dx][c] = bc[dy * WW + dx] * PSC;
    }
}

static __device__ __forceinline__ float ent9(const float s[9], float cc)
{
    float pr = ((s[0] * s[1]) * (s[2] * s[3])) *
               ((s[4] * s[5]) * (s[6] * s[7])) * s[8];
    return cc - LN2_9 * fast_lg2(pr);
}

__global__ void __launch_bounds__(128)
je_kernel(const float* __restrict__ in, float* __restrict__ out)
{
    int x = blockIdx.x * 32 + threadIdx.x;   // 0..191  (grid.x = 6)
    int y = blockIdx.y * 4  + threadIdx.y;   // 0..191  (grid.y = 48)
    int n = blockIdx.z;

    float* ob = out + (size_t)n * (SFN * 2) * HW + y * WW + x;

    // Border pixels: just zero all 8 output channels (out is poisoned 0xAA).
    if (x == 0 || x > 190 || y == 0 || y > 190) {
        #pragma unroll
        for (int q = 0; q < 8; ++q) ob[q * HW] = 0.0f;
        return;
    }

    const float* ibase = in + (size_t)n * (SFN * CCH) * HW + (y - 1) * WW + (x - 1);

    float e[36];   // exp(-50*d2) for previous frame, 36 off-diagonal pairs

    // ---- frame 0: marginal only, seed e[] ----
    {
        float p[9][3];
        load_pts(ibase, p);
        float s[9];
        #pragma unroll
        for (int i = 0; i < 9; ++i) s[i] = 1.0f;
        int k = 0;
        #pragma unroll
        for (int i = 0; i < 9; ++i)
            #pragma unroll
            for (int j = i + 1; j < 9; ++j) {
                float d0 = p[i][0] - p[j][0];
                float d1 = p[i][1] - p[j][1];
                float d2 = p[i][2] - p[j][2];
                float nt = -(d0 * d0);
                nt = fmaf(-d1, d1, nt);
                nt = fmaf(-d2, d2, nt);
                float ee = fast_ex2(nt);
                e[k] = ee;
                s[i] += ee;
                s[j] += ee;
                ++k;
            }
        ob[0] = ent9(s, CM);
    }

    // ---- frames 1..3: marginal(sf) + joint(sf-1) fused in one pair pass ----
    #pragma unroll
    for (int sf = 1; sf < SFN; ++sf) {
        float p[9][3];
        load_pts(ibase + sf * (CCH * HW), p);
        float s[9], sj[9];
        #pragma unroll
        for (int i = 0; i < 9; ++i) { s[i] = 1.0f; sj[i] = 1.0f; }
        int k = 0;
        #pragma unroll
        for (int i = 0; i < 9; ++i)
            #pragma unroll
            for (int j = i + 1; j < 9; ++j) {
                float d0 = p[i][0] - p[j][0];
                float d1 = p[i][1] - p[j][1];
                float d2 = p[i][2] - p[j][2];
                float nt = -(d0 * d0);
                nt = fmaf(-d1, d1, nt);
                nt = fmaf(-d2, d2, nt);
                float ee = fast_ex2(nt);
                float ej = e[k] * ee;   // joint exp = product of per-frame exps
                e[k] = ee;
                s[i]  += ee;  s[j]  += ee;
                sj[i] += ej;  sj[j] += ej;
                ++k;
            }
        ob[(2 * sf) * HW]     = ent9(s,  CM);
        ob[(2 * sf - 1) * HW] = ent9(sj, CJ);
    }

    // ---- last frame pairs with itself: joint exp = e^2 ----
    {
        float sj[9];
        #pragma unroll
        for (int i = 0; i < 9; ++i) sj[i] = 1.0f;
        int k = 0;
        #pragma unroll
        for (int i = 0; i < 9; ++i)
            #pragma unroll
            for (int j = i + 1; j < 9; ++j) {
                float ej = e[k] * e[k];
                sj[i] += ej;
                sj[j] += ej;
                ++k;
            }
        ob[7 * HW] = ent9(sj, CJ);
    }
}

extern "C" void kernel_launch(void* const* d_in, const int* in_sizes, int n_in,
                              void* d_out, int out_size)
{
    dim3 blk(32, 4, 1);
    dim3 grd(6, 48, NN);   // 192x192 pixels x 4 batches; borders zeroed in-kernel
    je_kernel<<<grd, blk>>>((const float*)d_in[0], (float*)d_out);
}